// round 2
// baseline (speedup 1.0000x reference)
#include <cuda_runtime.h>
#include <stdint.h>
#include <math.h>

// Problem dims
#define BQ 256
#define TQ 128
#define DETERQ 512
#define HIDQ 512
#define TOTQ 1024
#define OBSQ 768
#define ACTQ 7
#define FEATQ 3584   // 512 deter + 1024 stoch + 1024 prior + 1024 post

// JAX PRNG mode: 1 = threefry_partitionable (modern default), 0 = original
#define PRNG_PARTITIONABLE 1

// ---------------- device scratch (no allocations allowed) ----------------
__device__ float g_post_obs[(size_t)BQ * TQ * HIDQ];   // o_t @ post_w1[512:1280]  (67 MB)
__device__ float g_gh[BQ * 3 * DETERQ];                // deter @ w_hh + b_hh
__device__ float g_h[BQ * (HIDQ + HIDQ)];              // [elu prior hidden | elu post hidden]
__device__ float g_deter[BQ * DETERQ];
__device__ int   g_idx[BQ * 32];
__device__ uint2 g_keys[TQ];

// ---------------- threefry2x32 (JAX-exact, 20 rounds) ----------------
__device__ __forceinline__ uint32_t rotl32(uint32_t x, int d) {
    return (x << d) | (x >> (32 - d));
}
__device__ __forceinline__ void tf_round4(uint32_t& x0, uint32_t& x1,
                                          int r0, int r1, int r2, int r3) {
    x0 += x1; x1 = rotl32(x1, r0); x1 ^= x0;
    x0 += x1; x1 = rotl32(x1, r1); x1 ^= x0;
    x0 += x1; x1 = rotl32(x1, r2); x1 ^= x0;
    x0 += x1; x1 = rotl32(x1, r3); x1 ^= x0;
}
__device__ __forceinline__ void threefry2x32(uint32_t k0, uint32_t k1,
                                             uint32_t c0, uint32_t c1,
                                             uint32_t& o0, uint32_t& o1) {
    uint32_t ks2 = k0 ^ k1 ^ 0x1BD11BDAu;
    uint32_t x0 = c0 + k0, x1 = c1 + k1;
    tf_round4(x0, x1, 13, 15, 26, 6);  x0 += k1;  x1 += ks2 + 1u;
    tf_round4(x0, x1, 17, 29, 16, 24); x0 += ks2; x1 += k0 + 2u;
    tf_round4(x0, x1, 13, 15, 26, 6);  x0 += k0;  x1 += k1 + 3u;
    tf_round4(x0, x1, 17, 29, 16, 24); x0 += k1;  x1 += ks2 + 4u;
    tf_round4(x0, x1, 13, 15, 26, 6);  x0 += ks2; x1 += k0 + 5u;
    o0 = x0; o1 = x1;
}

// ---------------- init: zero deter, derive per-step keys from key(42) ----------------
__global__ void init_kernel() {
    int i = blockIdx.x * 256 + threadIdx.x;
    if (i < BQ * DETERQ) g_deter[i] = 0.0f;
    if (blockIdx.x == 0 && threadIdx.x < TQ) {
        uint32_t t = threadIdx.x;
        uint32_t o0, o1;
#if PRNG_PARTITIONABLE
        // fold-like split: key_t = threefry((0,42), (hi=0, lo=t))
        threefry2x32(0u, 42u, 0u, t, o0, o1);
        g_keys[t] = make_uint2(o0, o1);
#else
        // original split: bits = threefry((0,42), iota(2T)); key_t = (bits[2t], bits[2t+1])
        uint32_t r[2];
        for (int q = 0; q < 2; q++) {
            uint32_t i2 = 2u * t + (uint32_t)q;
            uint32_t a, b;
            if (i2 < (uint32_t)TQ) { threefry2x32(0u, 42u, i2, i2 + TQ, a, b); r[q] = a; }
            else                   { threefry2x32(0u, 42u, i2 - TQ, i2, a, b); r[q] = b; }
        }
        g_keys[t] = make_uint2(r[0], r[1]);
#endif
    }
}

// ---------------- generic fp32 GEMM with split-N + epilogue ----------------
// C[M,N] = A[M,K] @ B[K,N] (+bias) (+extra for second half) (optional ELU)
// For n >= nsplit: use B2/bias2, A column offset acol2, extra2 add.
struct GemmP {
    const float* A; int lda; int acol2;
    const float* B1; const float* B2; int ldb;
    const float* bias1; const float* bias2;
    const float* extra2; int ld_extra;
    float* C; long long ldc;
    int M, N, K, nsplit;
    int act;   // 0 = none, 1 = ELU
};

__global__ __launch_bounds__(128) void gemm_kernel(GemmP p) {
    __shared__ __align__(16) float As[16][36];
    __shared__ __align__(16) float Bs[16][64];
    int bn = blockIdx.x * 64;
    int bm = blockIdx.y * 32;
    bool second = (bn >= p.nsplit);
    const float* B    = second ? p.B2 : p.B1;
    const float* bias = second ? p.bias2 : p.bias1;
    const float* A    = p.A + (second ? p.acol2 : 0);
    int bcol = second ? (bn - p.nsplit) : bn;

    int tid = threadIdx.x;
    int tx = tid & 15, ty = tid >> 4;

    float acc[4][4];
#pragma unroll
    for (int i = 0; i < 4; i++)
#pragma unroll
        for (int j = 0; j < 4; j++) acc[i][j] = 0.0f;

    int arow = tid >> 2;            // 0..31
    int akq  = (tid & 3) << 2;      // 0,4,8,12
    int bk   = tid >> 4;            // 0..7
    int bnn  = (tid & 15) << 2;     // 0..60

    const float* aptr = A + (size_t)(bm + arow) * p.lda + akq;
    const float* bptr = B + (size_t)bk * p.ldb + bcol + bnn;

    float4 av  = *(const float4*)(aptr);
    float4 bv0 = *(const float4*)(bptr);
    float4 bv1 = *(const float4*)(bptr + 8 * (size_t)p.ldb);

    for (int k0 = 0; k0 < p.K; k0 += 16) {
        As[akq + 0][arow] = av.x;
        As[akq + 1][arow] = av.y;
        As[akq + 2][arow] = av.z;
        As[akq + 3][arow] = av.w;
        *(float4*)&Bs[bk][bnn]     = bv0;
        *(float4*)&Bs[bk + 8][bnn] = bv1;
        __syncthreads();

        if (k0 + 16 < p.K) {
            av  = *(const float4*)(aptr + k0 + 16);
            bv0 = *(const float4*)(bptr + (size_t)(k0 + 16) * p.ldb);
            bv1 = *(const float4*)(bptr + (size_t)(k0 + 24) * p.ldb);
        }
#pragma unroll
        for (int kk = 0; kk < 16; kk++) {
            float a0 = As[kk][ty * 4 + 0], a1 = As[kk][ty * 4 + 1];
            float a2 = As[kk][ty * 4 + 2], a3 = As[kk][ty * 4 + 3];
            float b0 = Bs[kk][tx * 4 + 0], b1 = Bs[kk][tx * 4 + 1];
            float b2 = Bs[kk][tx * 4 + 2], b3 = Bs[kk][tx * 4 + 3];
            acc[0][0] += a0 * b0; acc[0][1] += a0 * b1; acc[0][2] += a0 * b2; acc[0][3] += a0 * b3;
            acc[1][0] += a1 * b0; acc[1][1] += a1 * b1; acc[1][2] += a1 * b2; acc[1][3] += a1 * b3;
            acc[2][0] += a2 * b0; acc[2][1] += a2 * b1; acc[2][2] += a2 * b2; acc[2][3] += a2 * b3;
            acc[3][0] += a3 * b0; acc[3][1] += a3 * b1; acc[3][2] += a3 * b2; acc[3][3] += a3 * b3;
        }
        __syncthreads();
    }

#pragma unroll
    for (int i = 0; i < 4; i++) {
        int row = bm + ty * 4 + i;
#pragma unroll
        for (int j = 0; j < 4; j++) {
            int cl = bcol + tx * 4 + j;     // local col within half
            float v = acc[i][j];
            if (bias) v += bias[cl];
            if (second && p.extra2) v += p.extra2[(size_t)row * p.ld_extra + cl];
            if (p.act == 1) v = (v > 0.0f) ? v : expm1f(v);
            p.C[(size_t)row * (size_t)p.ldc + bn + tx * 4 + j] = v;
        }
    }
}

// ---------------- gather-sum gi + GRU pointwise, writes deter to scratch + out ----------------
__global__ void gru_kernel(const float* __restrict__ w_ih,
                           const float* __restrict__ b_ih,
                           const float* __restrict__ actions,
                           float* __restrict__ out, int t) {
    int b = blockIdx.y;
    int d = blockIdx.x * 256 + threadIdx.x;
    __shared__ int   sidx[32];
    __shared__ float sact[ACTQ];
    if (threadIdx.x < 32) sidx[threadIdx.x] = g_idx[b * 32 + threadIdx.x];
    if (threadIdx.x < ACTQ)
        sact[threadIdx.x] = actions[((size_t)b * TQ + t) * ACTQ + threadIdx.x];
    __syncthreads();

    float gr = b_ih[d], gz = b_ih[DETERQ + d], gn = b_ih[2 * DETERQ + d];
    if (t > 0) {
#pragma unroll 4
        for (int s = 0; s < 32; s++) {
            const float* wr = w_ih + (size_t)(s * 32 + sidx[s]) * (3 * DETERQ);
            gr += wr[d]; gz += wr[DETERQ + d]; gn += wr[2 * DETERQ + d];
        }
    }
#pragma unroll
    for (int j = 0; j < ACTQ; j++) {
        const float* wr = w_ih + (size_t)(TOTQ + j) * (3 * DETERQ);
        float a = sact[j];
        gr += a * wr[d]; gz += a * wr[DETERQ + d]; gn += a * wr[2 * DETERQ + d];
    }
    float hr = g_gh[b * 3 * DETERQ + d];
    float hz = g_gh[b * 3 * DETERQ + DETERQ + d];
    float hn = g_gh[b * 3 * DETERQ + 2 * DETERQ + d];
    float r = 1.0f / (1.0f + expf(-(gr + hr)));
    float z = 1.0f / (1.0f + expf(-(gz + hz)));
    float n = tanhf(gn + r * hn);
    float dprev = g_deter[b * DETERQ + d];
    float dn = (1.0f - z) * n + z * dprev;
    g_deter[b * DETERQ + d] = dn;
    out[((size_t)b * TQ + t) * FEATQ + d] = dn;
}

// ---------------- gumbel-max categorical sampler (one warp per (b,s)) ----------------
__global__ void sample_kernel(float* __restrict__ out, int t) {
    int gwarp = (blockIdx.x * 256 + threadIdx.x) >> 5;   // 0..8191
    int lane = threadIdx.x & 31;
    int b = gwarp >> 5;
    int s = gwarp & 31;
    uint2 key = g_keys[t];
    uint32_t e = ((uint32_t)b << 10) | ((uint32_t)s << 5) | (uint32_t)lane;
    uint32_t o0, o1, bits;
#if PRNG_PARTITIONABLE
    threefry2x32(key.x, key.y, 0u, e, o0, o1);
    bits = o0 ^ o1;
#else
    const uint32_t halfn = (uint32_t)(BQ * 32 * 32) / 2u;
    if (e < halfn) { threefry2x32(key.x, key.y, e, e + halfn, o0, o1); bits = o0; }
    else           { threefry2x32(key.x, key.y, e - halfn, e, o0, o1); bits = o1; }
#endif
    float f = __uint_as_float((bits >> 9) | 0x3f800000u) - 1.0f;
    const float tinyv = 1.17549435e-38f;
    float u = fmaxf(tinyv, f);
    float g = -logf(-logf(u));

    size_t rowoff = ((size_t)b * TQ + t) * FEATQ;
    float v = out[rowoff + 2560 + s * 32 + lane] + g;   // post logits
    int idx = lane;
#pragma unroll
    for (int off = 16; off > 0; off >>= 1) {
        float ov = __shfl_down_sync(0xffffffffu, v, off);
        int   oi = __shfl_down_sync(0xffffffffu, idx, off);
        if (ov > v || (ov == v && oi < idx)) { v = ov; idx = oi; }
    }
    int w = __shfl_sync(0xffffffffu, idx, 0);
    out[rowoff + 512 + s * 32 + lane] = (lane == w) ? 1.0f : 0.0f;  // stoch one-hot
    if (lane == 0) g_idx[b * 32 + s] = w;
}

// ---------------- host launcher ----------------
extern "C" void kernel_launch(void* const* d_in, const int* in_sizes, int n_in,
                              void* d_out, int out_size) {
    (void)in_sizes; (void)n_in; (void)out_size;
    const float* obs      = (const float*)d_in[0];
    const float* actions  = (const float*)d_in[1];
    const float* w_ih     = (const float*)d_in[2];
    const float* w_hh     = (const float*)d_in[3];
    const float* b_ih     = (const float*)d_in[4];
    const float* b_hh     = (const float*)d_in[5];
    const float* prior_w1 = (const float*)d_in[6];
    const float* prior_b1 = (const float*)d_in[7];
    const float* prior_w2 = (const float*)d_in[8];
    const float* prior_b2 = (const float*)d_in[9];
    const float* post_w1  = (const float*)d_in[10];
    const float* post_b1  = (const float*)d_in[11];
    const float* post_w2  = (const float*)d_in[12];
    const float* post_b2  = (const float*)d_in[13];
    float* out = (float*)d_out;

    void *p_po, *p_gh, *p_h, *p_deter;
    cudaGetSymbolAddress(&p_po, g_post_obs);
    cudaGetSymbolAddress(&p_gh, g_gh);
    cudaGetSymbolAddress(&p_h, g_h);
    cudaGetSymbolAddress(&p_deter, g_deter);
    float* post_obs = (float*)p_po;
    float* gh    = (float*)p_gh;
    float* h     = (float*)p_h;
    float* deter = (float*)p_deter;

    init_kernel<<<512, 256>>>();

    // Hoisted: post_obs[b*T+t, :] = o_t @ post_w1[512:1280, :]   (bias added later)
    {
        GemmP p;
        p.A = obs; p.lda = OBSQ; p.acol2 = 0;
        p.B1 = post_w1 + (size_t)DETERQ * HIDQ; p.B2 = nullptr; p.ldb = HIDQ;
        p.bias1 = nullptr; p.bias2 = nullptr;
        p.extra2 = nullptr; p.ld_extra = 0;
        p.C = post_obs; p.ldc = HIDQ;
        p.M = BQ * TQ; p.N = HIDQ; p.K = OBSQ; p.nsplit = 1 << 30; p.act = 0;
        gemm_kernel<<<dim3(HIDQ / 64, (BQ * TQ) / 32), 128>>>(p);
    }

    for (int t = 0; t < TQ; t++) {
        // gh = deter @ w_hh + b_hh
        {
            GemmP p;
            p.A = deter; p.lda = DETERQ; p.acol2 = 0;
            p.B1 = w_hh; p.B2 = nullptr; p.ldb = 3 * DETERQ;
            p.bias1 = b_hh; p.bias2 = nullptr;
            p.extra2 = nullptr; p.ld_extra = 0;
            p.C = gh; p.ldc = 3 * DETERQ;
            p.M = BQ; p.N = 3 * DETERQ; p.K = DETERQ; p.nsplit = 1 << 30; p.act = 0;
            gemm_kernel<<<dim3((3 * DETERQ) / 64, BQ / 32), 128>>>(p);
        }
        // gi (gather-sum of one-hot rows + action) + GRU pointwise -> deter, out[:,t,0:512]
        gru_kernel<<<dim3(DETERQ / 256, BQ), 256>>>(w_ih, b_ih, actions, out, t);

        // h = [ elu(deter@prior_w1 + b1) | elu(deter@post_w1[0:512] + post_obs + b1) ]
        {
            GemmP p;
            p.A = deter; p.lda = DETERQ; p.acol2 = 0;
            p.B1 = prior_w1; p.B2 = post_w1; p.ldb = HIDQ;
            p.bias1 = prior_b1; p.bias2 = post_b1;
            p.extra2 = post_obs + (size_t)t * HIDQ; p.ld_extra = TQ * HIDQ;
            p.C = h; p.ldc = 2 * HIDQ;
            p.M = BQ; p.N = 2 * HIDQ; p.K = DETERQ; p.nsplit = HIDQ; p.act = 1;
            gemm_kernel<<<dim3((2 * HIDQ) / 64, BQ / 32), 128>>>(p);
        }
        // [prior_logits | post_logits] -> out[:,t,1536:3584]
        {
            GemmP p;
            p.A = h; p.lda = 2 * HIDQ; p.acol2 = HIDQ;
            p.B1 = prior_w2; p.B2 = post_w2; p.ldb = TOTQ;
            p.bias1 = prior_b2; p.bias2 = post_b2;
            p.extra2 = nullptr; p.ld_extra = 0;
            p.C = out + (size_t)t * FEATQ + 1536; p.ldc = (long long)TQ * FEATQ;
            p.M = BQ; p.N = 2 * TOTQ; p.K = HIDQ; p.nsplit = TOTQ; p.act = 0;
            gemm_kernel<<<dim3((2 * TOTQ) / 64, BQ / 32), 128>>>(p);
        }
        // categorical sample + one-hot stoch -> out[:,t,512:1536], g_idx
        sample_kernel<<<(BQ * 32) / 8, 256>>>(out, t);
    }
}